// round 11
// baseline (speedup 1.0000x reference)
#include <cuda_runtime.h>
#include <cuda_bf16.h>

// Problem constants (fixed by the reference)
#define Bdim 2
#define Ndim 4096
#define FIN  256
#define FO   64
#define NH   4
#define ROWS (Bdim * Ndim)   // 8192

#define TI 16               // i-rows per block
#define TJ 64               // j-cols per tile
#define NJT (Ndim / TJ)     // 64 j-tiles
#define NT (Ndim / 32)      // 128 mask words per row

// -------- device scratch (no allocation allowed) --------
__device__ float         g_X   [ROWS * FO];          // (B,N,64) = h @ W
__device__ float2        g_elEF[ROWS * NH];          // {exp(el), exp(0.2*el)}
__device__ float2        g_erEF[ROWS * NH];          // {exp(er), exp(0.2*er)}  (j,h) contiguous
__device__ __nv_bfloat16 g_XTh[ROWS * FO];           // X^T hi, [b][n(64)][j(4096)]
__device__ __nv_bfloat16 g_XTl[ROWS * FO];           // X^T lo
__device__ unsigned      g_mask[ROWS * NT];          // adjacency bitmask [row][jword]

// -------- helpers --------
__device__ __forceinline__ unsigned pack_bf16x2(float lo, float hi) {
    unsigned r;
    asm("cvt.rn.bf16x2.f32 %0, %1, %2;" : "=r"(r) : "f"(hi), "f"(lo));
    return r;
}
__device__ __forceinline__ float bf16lo_f(unsigned v) { return __uint_as_float(v << 16); }
__device__ __forceinline__ float bf16hi_f(unsigned v) { return __uint_as_float(v & 0xffff0000u); }

__device__ __forceinline__ unsigned long long pk2(float a, float b) {
    unsigned long long r;
    asm("mov.b64 %0, {%1, %2};"
        : "=l"(r) : "r"(__float_as_uint(a)), "r"(__float_as_uint(b)));
    return r;
}
__device__ __forceinline__ float2 upk2(unsigned long long v) {
    unsigned int lo, hi;
    asm("mov.b64 {%0, %1}, %2;" : "=r"(lo), "=r"(hi) : "l"(v));
    return make_float2(__uint_as_float(lo), __uint_as_float(hi));
}
__device__ __forceinline__ unsigned long long mul2(unsigned long long a,
                                                   unsigned long long b) {
    unsigned long long d;
    asm("mul.rn.f32x2 %0, %1, %2;" : "=l"(d) : "l"(a), "l"(b));
    return d;
}

__device__ __forceinline__ void mma_bf16(float* c, const unsigned* a,
                                         unsigned b0, unsigned b1) {
    asm volatile(
        "mma.sync.aligned.m16n8k16.row.col.f32.bf16.bf16.f32 "
        "{%0,%1,%2,%3}, {%4,%5,%6,%7}, {%8,%9}, {%0,%1,%2,%3};"
        : "+f"(c[0]), "+f"(c[1]), "+f"(c[2]), "+f"(c[3])
        : "r"(a[0]), "r"(a[1]), "r"(a[2]), "r"(a[3]), "r"(b0), "r"(b1));
}
__device__ __forceinline__ void ldsm4(unsigned& r0, unsigned& r1,
                                      unsigned& r2, unsigned& r3, unsigned addr) {
    asm volatile("ldmatrix.sync.aligned.m8n8.x4.shared.b16 {%0,%1,%2,%3}, [%4];"
                 : "=r"(r0), "=r"(r1), "=r"(r2), "=r"(r3) : "r"(addr));
}
__device__ __forceinline__ void cp16(unsigned saddr, const void* g) {
    asm volatile("cp.async.cg.shared.global [%0], [%1], 16;\n" :: "r"(saddr), "l"(g));
}
__device__ __forceinline__ void cp8(unsigned saddr, const void* g) {
    asm volatile("cp.async.ca.shared.global [%0], [%1], 8;\n" :: "r"(saddr), "l"(g));
}
__device__ __forceinline__ void cp_commit() { asm volatile("cp.async.commit_group;\n" ::); }
__device__ __forceinline__ void cp_wait0()  { asm volatile("cp.async.wait_group 0;\n" ::); }

// ---------------- Kernel A: X = h @ W, fused transpose + bf16 hi/lo split ----
__global__ __launch_bounds__(256) void k_gemm_xw(const float* __restrict__ h,
                                                 const float* __restrict__ W) {
    __shared__ float sh[64][33];
    __shared__ float sw[32][64];
    __shared__ float ts[64][65];   // staging tile [row_local][feature]

    const int tid  = threadIdx.x;
    const int tx   = tid & 15;
    const int ty   = tid >> 4;
    const int row0 = blockIdx.x * 64;

    float acc[4][4];
#pragma unroll
    for (int i = 0; i < 4; i++)
#pragma unroll
        for (int j = 0; j < 4; j++) acc[i][j] = 0.0f;

    for (int k0 = 0; k0 < FIN; k0 += 32) {
        __syncthreads();
#pragma unroll
        for (int m = 0; m < 8; m++) {
            int idx = tid + 256 * m;
            sh[idx >> 5][idx & 31] =
                h[(size_t)(row0 + (idx >> 5)) * FIN + k0 + (idx & 31)];
            sw[idx >> 6][idx & 63] = W[(size_t)(k0 + (idx >> 6)) * FO + (idx & 63)];
        }
        __syncthreads();
#pragma unroll
        for (int kk = 0; kk < 32; kk++) {
            float a[4];
#pragma unroll
            for (int i = 0; i < 4; i++) a[i] = sh[ty * 4 + i][kk];
            float4 bb = *(const float4*)&sw[kk][tx * 4];
#pragma unroll
            for (int i = 0; i < 4; i++) {
                acc[i][0] = fmaf(a[i], bb.x, acc[i][0]);
                acc[i][1] = fmaf(a[i], bb.y, acc[i][1]);
                acc[i][2] = fmaf(a[i], bb.z, acc[i][2]);
                acc[i][3] = fmaf(a[i], bb.w, acc[i][3]);
            }
        }
    }
#pragma unroll
    for (int i = 0; i < 4; i++) {
        *(float4*)&g_X[(size_t)(row0 + ty * 4 + i) * FO + tx * 4] =
            make_float4(acc[i][0], acc[i][1], acc[i][2], acc[i][3]);
#pragma unroll
        for (int j = 0; j < 4; j++) ts[ty * 4 + i][tx * 4 + j] = acc[i][j];
    }
    __syncthreads();

    const int n    = tid >> 2;
    const int part = tid & 3;
    const int b    = row0 >> 12;
    const int jloc = row0 & 4095;
    size_t base = ((size_t)(b * 64 + n) * Ndim + jloc + part * 16);
#pragma unroll
    for (int jj = 0; jj < 16; jj += 2) {
        float v0 = ts[part * 16 + jj][n];
        float v1 = ts[part * 16 + jj + 1][n];
        unsigned hpack = pack_bf16x2(v0, v1);
        float r0f = v0 - bf16lo_f(hpack);
        float r1f = v1 - bf16hi_f(hpack);
        unsigned lpack = pack_bf16x2(r0f, r1f);
        *(unsigned*)((char*)g_XTh + (base + jj) * 2) = hpack;
        *(unsigned*)((char*)g_XTl + (base + jj) * 2) = lpack;
    }
}

// ---------------- Kernel B: attention coefficients -> exp pairs ----------------
__global__ __launch_bounds__(128) void k_coef(const float* __restrict__ Wl,
                                              const float* __restrict__ Wr) {
    const int row  = blockIdx.x * 4 + (threadIdx.x >> 5);
    const int lane = threadIdx.x & 31;
    float2 x2 = *(const float2*)&g_X[(size_t)row * FO + lane * 2];
#pragma unroll
    for (int hh = 0; hh < NH; hh++) {
        float2 wl = *(const float2*)&Wl[hh * FO + lane * 2];
        float v = x2.x * wl.x + x2.y * wl.y;
#pragma unroll
        for (int o = 16; o > 0; o >>= 1) v += __shfl_xor_sync(0xffffffffu, v, o);
        float2 wr = *(const float2*)&Wr[hh * FO + lane * 2];
        float u = x2.x * wr.x + x2.y * wr.y;
#pragma unroll
        for (int o = 16; o > 0; o >>= 1) u += __shfl_xor_sync(0xffffffffu, u, o);
        if (lane == 0) {
            g_elEF[row * NH + hh] = make_float2(__expf(v), __expf(0.2f * v));
            g_erEF[row * NH + hh] = make_float2(__expf(u), __expf(0.2f * u));
        }
    }
}

// ---------------- Kernel D: pack adjacency to bitmasks ----------------
__global__ __launch_bounds__(256) void k_pack(const int* __restrict__ adj) {
    const int lane = threadIdx.x & 31;
    const int wgl  = (blockIdx.x * 8) + (threadIdx.x >> 5);
#pragma unroll 4
    for (int it = 0; it < 128; it++) {
        int word = wgl + it * 8192;
        int v = adj[(size_t)word * 32 + lane];
        unsigned m = __ballot_sync(0xffffffffu, v != 0);
        if (lane == 0) g_mask[word] = m;
    }
}

// ---------------- Kernel E: fused attention + PV ----------------
// TI=16, 128 threads (warp w = head w), 4 blocks/SM for cross-block stall hiding.
#define XS_STRIDE 144                  // 128B data + 16B pad per n-row
#define XS_BYTES  (64 * XS_STRIDE)     // 9216 per stage per array
#define ER_CNT    (NH * TJ)            // float2 entries per stage, [h][j]
__global__ __launch_bounds__(128, 4) void k_attn(const float* __restrict__ bias,
                                                 float* __restrict__ out) {
    __shared__ __align__(16) unsigned char sXh[2][XS_BYTES];
    __shared__ __align__(16) unsigned char sXl[2][XS_BYTES];
    __shared__ __align__(16) float2 erS[2][ER_CNT];

    const int tid  = threadIdx.x;
    const int w    = tid >> 5;
    const int lane = tid & 31;
    const int g    = lane >> 2;
    const int q    = lane & 3;
    const int q2   = q * 2;

    const int bb = blockIdx.x >> 8;            // 256 i-tiles per batch
    const int i0 = (blockIdx.x & 255) * TI;
    const int hh = w;                          // warp = head
    const int iA = i0 + g;                     // rows iA and iA+8

    const float2 efAf = g_elEF[((bb << 12) + iA) * NH + hh];
    const float2 efBf = g_elEF[((bb << 12) + iA + 8) * NH + hh];
    const unsigned long long efA64 = pk2(efAf.x, efAf.y);
    const unsigned long long efB64 = pk2(efBf.x, efBf.y);
    const uint2* mrowA = (const uint2*)&g_mask[(size_t)((bb << 12) + iA) * NT];
    const uint2* mrowB = (const uint2*)&g_mask[(size_t)((bb << 12) + iA + 8) * NT];

    float acc[8][4];
#pragma unroll
    for (int n = 0; n < 8; n++)
#pragma unroll
        for (int k = 0; k < 4; k++) acc[n][k] = 0.0f;
    float den0 = 0.0f, den1 = 0.0f;

    const char* XThB = (const char*)(g_XTh + (size_t)bb * 64 * Ndim);
    const char* XTlB = (const char*)(g_XTl + (size_t)bb * 64 * Ndim);
    const float2* erB = g_erEF + (size_t)(bb << 12) * NH;

    // staging mapping: 128 threads; X rows (feature n = tid>>1), 64B half sp = tid&1
    const int sn = tid >> 1;
    const int sp = tid & 1;
    const unsigned aXh = (unsigned)__cvta_generic_to_shared(&sXh[0][0]);
    const unsigned aXl = (unsigned)__cvta_generic_to_shared(&sXl[0][0]);
    const unsigned aEr = (unsigned)__cvta_generic_to_shared(&erS[0][0]);
    const unsigned dstOff = sn * XS_STRIDE + sp * 64;
    const size_t   srcOff = ((size_t)sn * Ndim + sp * 32) * 2;   // bytes, + j0*2
    // er staging: thread -> (j = tid>>1, two heads hb, hb+1); dst [h][j]
    const int      erJ   = tid >> 1;
    const int      erHb  = (tid & 1) * 2;
    const size_t   erSrc = ((size_t)erJ * NH + erHb) * 8;        // bytes, + j0*NH*8
    const unsigned erD0  = (erHb * TJ + erJ) * 8;
    const unsigned erD1  = ((erHb + 1) * TJ + erJ) * 8;
    // ldmatrix lane base: row (lane&7), 16B chunk (lane>>3)
    const unsigned lb = (lane & 7) * XS_STRIDE + (lane >> 3) * 16;

    // prologue: stage tile 0
    {
#pragma unroll
        for (int c = 0; c < 4; c++) {
            cp16(aXh + dstOff + c * 16, XThB + srcOff + c * 16);
            cp16(aXl + dstOff + c * 16, XTlB + srcOff + c * 16);
        }
        cp8(aEr + erD0, (const char*)erB + erSrc);
        cp8(aEr + erD1, (const char*)erB + erSrc + 8);
        cp_commit();
    }

    uint2 mwA = mrowA[0];
    uint2 mwB = mrowB[0];

    for (int jt = 0; jt < NJT; jt++) {
        const int st = jt & 1;
        cp_wait0();
        __syncthreads();

        if (jt + 1 < NJT) {
            const size_t jb = (size_t)(jt + 1) * TJ * 2;       // bytes along j
            const unsigned so = (st ^ 1) * XS_BYTES + dstOff;
#pragma unroll
            for (int c = 0; c < 4; c++) {
                cp16(aXh + so + c * 16, XThB + srcOff + jb + c * 16);
                cp16(aXl + so + c * 16, XTlB + srcOff + jb + c * 16);
            }
            const size_t ejb = (size_t)(jt + 1) * TJ * NH * 8;
            cp8(aEr + (st ^ 1) * (ER_CNT * 8) + erD0, (const char*)erB + erSrc + ejb);
            cp8(aEr + (st ^ 1) * (ER_CNT * 8) + erD1, (const char*)erB + erSrc + ejb + 8);
        }
        cp_commit();

        uint2 nmwA = make_uint2(0, 0), nmwB = make_uint2(0, 0);
        if (jt + 1 < NJT) { nmwA = mrowA[jt + 1]; nmwB = mrowB[jt + 1]; }

        const unsigned long long* erU =
            (const unsigned long long*)(erS[st] + hh * TJ);
        const unsigned xhB = aXh + st * XS_BYTES + lb;
        const unsigned xlB = aXl + st * XS_BYTES + lb;

#pragma unroll
        for (int ktp = 0; ktp < 2; ktp++) {
            const unsigned wA = ktp ? mwA.y : mwA.x;
            const unsigned wB = ktp ? mwB.y : mwB.x;

            unsigned aH[2][4], aL[2][4];
#pragma unroll
            for (int s = 0; s < 2; s++) {
                const int cb = ktp * 32 + s * 16 + q2;
                unsigned long long e0 = erU[cb];
                unsigned long long e1 = erU[cb + 1];
                unsigned long long e2 = erU[cb + 8];
                unsigned long long e3 = erU[cb + 9];

                unsigned msA = wA >> (s * 16 + q2);
                unsigned msB = wB >> (s * 16 + q2);

                float2 fA0 = upk2(mul2(efA64, e0));
                float2 fA1 = upk2(mul2(efA64, e1));
                float2 fA2 = upk2(mul2(efA64, e2));
                float2 fA3 = upk2(mul2(efA64, e3));
                float2 fB0 = upk2(mul2(efB64, e0));
                float2 fB1 = upk2(mul2(efB64, e1));
                float2 fB2 = upk2(mul2(efB64, e2));
                float2 fB3 = upk2(mul2(efB64, e3));

                float pA0 = (msA & 1u)   ? fmaxf(fA0.x, fA0.y) : 0.0f;
                float pA1 = (msA & 2u)   ? fmaxf(fA1.x, fA1.y) : 0.0f;
                float pA2 = (msA & 256u) ? fmaxf(fA2.x, fA2.y) : 0.0f;
                float pA3 = (msA & 512u) ? fmaxf(fA3.x, fA3.y) : 0.0f;
                float pB0 = (msB & 1u)   ? fmaxf(fB0.x, fB0.y) : 0.0f;
                float pB1 = (msB & 2u)   ? fmaxf(fB1.x, fB1.y) : 0.0f;
                float pB2 = (msB & 256u) ? fmaxf(fB2.x, fB2.y) : 0.0f;
                float pB3 = (msB & 512u) ? fmaxf(fB3.x, fB3.y) : 0.0f;

                den0 += (pA0 + pA1) + (pA2 + pA3);
                den1 += (pB0 + pB1) + (pB2 + pB3);

                aH[s][0] = pack_bf16x2(pA0, pA1);
                aH[s][1] = pack_bf16x2(pB0, pB1);
                aH[s][2] = pack_bf16x2(pA2, pA3);
                aH[s][3] = pack_bf16x2(pB2, pB3);
                aL[s][0] = pack_bf16x2(pA0 - bf16lo_f(aH[s][0]), pA1 - bf16hi_f(aH[s][0]));
                aL[s][1] = pack_bf16x2(pB0 - bf16lo_f(aH[s][1]), pB1 - bf16hi_f(aH[s][1]));
                aL[s][2] = pack_bf16x2(pA2 - bf16lo_f(aH[s][2]), pA3 - bf16hi_f(aH[s][2]));
                aL[s][3] = pack_bf16x2(pB2 - bf16lo_f(aH[s][3]), pB3 - bf16hi_f(aH[s][3]));
            }

            const unsigned kb = ktp * 64;   // byte offset of this kt-pair along j
#pragma unroll
            for (int nt = 0; nt < 8; nt++) {
                const unsigned ro = nt * (8 * XS_STRIDE) + kb;
                unsigned bh0, bh1, bh2, bh3, bl0, bl1, bl2, bl3;
                ldsm4(bh0, bh1, bh2, bh3, xhB + ro);
                ldsm4(bl0, bl1, bl2, bl3, xlB + ro);
                mma_bf16(acc[nt], aH[0], bh0, bh1);
                mma_bf16(acc[nt], aH[0], bl0, bl1);
                mma_bf16(acc[nt], aL[0], bh0, bh1);
                mma_bf16(acc[nt], aH[1], bh2, bh3);
                mma_bf16(acc[nt], aH[1], bl2, bl3);
                mma_bf16(acc[nt], aL[1], bh2, bh3);
            }
        }
        mwA = nmwA;
        mwB = nmwB;
    }

    // reduce denominators across the 4 lanes of each row group
    den0 += __shfl_xor_sync(0xffffffffu, den0, 1);
    den0 += __shfl_xor_sync(0xffffffffu, den0, 2);
    den1 += __shfl_xor_sync(0xffffffffu, den1, 1);
    den1 += __shfl_xor_sync(0xffffffffu, den1, 2);
    const float inv0 = 1.0f / den0;
    const float inv1 = 1.0f / den1;

    float* o0 = out + (size_t)((bb << 12) + iA) * (NH * FO) + hh * FO;
    float* o1 = o0 + (size_t)8 * (NH * FO);
#pragma unroll
    for (int nt = 0; nt < 8; nt++) {
        const int col = nt * 8 + q2;
        float2 bv = *(const float2*)&bias[hh * FO + col];
        float v00 = fmaf(acc[nt][0], inv0, bv.x);
        float v01 = fmaf(acc[nt][1], inv0, bv.y);
        float v10 = fmaf(acc[nt][2], inv1, bv.x);
        float v11 = fmaf(acc[nt][3], inv1, bv.y);
        v00 = v00 > 0.0f ? v00 : expm1f(v00);
        v01 = v01 > 0.0f ? v01 : expm1f(v01);
        v10 = v10 > 0.0f ? v10 : expm1f(v10);
        v11 = v11 > 0.0f ? v11 : expm1f(v11);
        *(float2*)&o0[col] = make_float2(v00, v01);
        *(float2*)&o1[col] = make_float2(v10, v11);
    }
}

// ---------------- launch ----------------
extern "C" void kernel_launch(void* const* d_in, const int* in_sizes, int n_in,
                              void* d_out, int out_size) {
    const int*   adj = (const int*)  d_in[0];  // (B,N,N) int32
    const float* h   = (const float*)d_in[1];  // (B,N,256)
    const float* W   = (const float*)d_in[2];  // (256,64)
    const float* Wl  = (const float*)d_in[3];  // (4,64)
    const float* Wr  = (const float*)d_in[4];  // (4,64)
    const float* bia = (const float*)d_in[5];  // (64,)
    float* out = (float*)d_out;                // (B,N,256)

    k_pack<<<1024, 256>>>(adj);
    k_gemm_xw<<<ROWS / 64, 256>>>(h, W);
    k_coef<<<ROWS / 4, 128>>>(Wl, Wr);
    k_attn<<<Bdim * (Ndim / TI), 128>>>(bia, out);
}

// round 13
// speedup vs baseline: 1.3816x; 1.3816x over previous
#include <cuda_runtime.h>
#include <cuda_fp16.h>

// Problem constants (fixed by the reference)
#define Bdim 2
#define Ndim 4096
#define FIN  256
#define FO   64
#define NH   4
#define ROWS (Bdim * Ndim)   // 8192

#define TI 32               // i-rows per block
#define TJ 64               // j-cols per tile
#define NJT (Ndim / TJ)     // 64 j-tiles
#define NT (Ndim / 32)      // 128 mask words per row

#define PSCALE 2.44140625e-4f   // 2^-12, folded into elEF; cancels in softmax

// -------- device scratch (no allocation allowed) --------
__device__ float  g_X   [ROWS * FO];          // (B,N,64) = h @ W
__device__ float2 g_elEF[ROWS * NH];          // {exp(el), exp(0.2*el)} * 2^-12
__device__ float2 g_erEF[ROWS * NH];          // {exp(er), exp(0.2*er)}  (j,h) contiguous
__device__ __half g_XTh[ROWS * FO];           // X^T hi (fp16), [b][n(64)][j(4096)]
__device__ __half g_XTl[ROWS * FO];           // X^T lo (fp16 residual)
__device__ unsigned g_mask[ROWS * NT];        // adjacency bitmask [row][jword]

// -------- helpers --------
__device__ __forceinline__ unsigned pack_f16x2(float lo, float hi) {
    unsigned r;
    asm("cvt.rn.f16x2.f32 %0, %1, %2;" : "=r"(r) : "f"(hi), "f"(lo));
    return r;
}
__device__ __forceinline__ float f16lo_f(unsigned v) {
    return __half2float(__ushort_as_half((unsigned short)(v & 0xffffu)));
}
__device__ __forceinline__ float f16hi_f(unsigned v) {
    return __half2float(__ushort_as_half((unsigned short)(v >> 16)));
}

__device__ __forceinline__ unsigned long long pk2(float a, float b) {
    unsigned long long r;
    asm("mov.b64 %0, {%1, %2};"
        : "=l"(r) : "r"(__float_as_uint(a)), "r"(__float_as_uint(b)));
    return r;
}
__device__ __forceinline__ float2 upk2(unsigned long long v) {
    unsigned int lo, hi;
    asm("mov.b64 {%0, %1}, %2;" : "=r"(lo), "=r"(hi) : "l"(v));
    return make_float2(__uint_as_float(lo), __uint_as_float(hi));
}
__device__ __forceinline__ unsigned long long mul2(unsigned long long a,
                                                   unsigned long long b) {
    unsigned long long d;
    asm("mul.rn.f32x2 %0, %1, %2;" : "=l"(d) : "l"(a), "l"(b));
    return d;
}

__device__ __forceinline__ void mma_f16(float* c, const unsigned* a,
                                        unsigned b0, unsigned b1) {
    asm volatile(
        "mma.sync.aligned.m16n8k16.row.col.f32.f16.f16.f32 "
        "{%0,%1,%2,%3}, {%4,%5,%6,%7}, {%8,%9}, {%0,%1,%2,%3};"
        : "+f"(c[0]), "+f"(c[1]), "+f"(c[2]), "+f"(c[3])
        : "r"(a[0]), "r"(a[1]), "r"(a[2]), "r"(a[3]), "r"(b0), "r"(b1));
}
__device__ __forceinline__ void ldsm4(unsigned& r0, unsigned& r1,
                                      unsigned& r2, unsigned& r3, unsigned addr) {
    asm volatile("ldmatrix.sync.aligned.m8n8.x4.shared.b16 {%0,%1,%2,%3}, [%4];"
                 : "=r"(r0), "=r"(r1), "=r"(r2), "=r"(r3) : "r"(addr));
}
__device__ __forceinline__ void cp16(unsigned saddr, const void* g) {
    asm volatile("cp.async.cg.shared.global [%0], [%1], 16;\n" :: "r"(saddr), "l"(g));
}
__device__ __forceinline__ void cp8(unsigned saddr, const void* g) {
    asm volatile("cp.async.ca.shared.global [%0], [%1], 8;\n" :: "r"(saddr), "l"(g));
}
__device__ __forceinline__ void cp_commit() { asm volatile("cp.async.commit_group;\n" ::); }
__device__ __forceinline__ void cp_wait0()  { asm volatile("cp.async.wait_group 0;\n" ::); }

// ---------------- Kernel A: X = h @ W, fused transpose + fp16 hi/lo split ----
__global__ __launch_bounds__(256) void k_gemm_xw(const float* __restrict__ h,
                                                 const float* __restrict__ W) {
    __shared__ float sh[64][33];
    __shared__ float sw[32][64];
    __shared__ float ts[64][65];   // staging tile [row_local][feature]

    const int tid  = threadIdx.x;
    const int tx   = tid & 15;
    const int ty   = tid >> 4;
    const int row0 = blockIdx.x * 64;

    float acc[4][4];
#pragma unroll
    for (int i = 0; i < 4; i++)
#pragma unroll
        for (int j = 0; j < 4; j++) acc[i][j] = 0.0f;

    for (int k0 = 0; k0 < FIN; k0 += 32) {
        __syncthreads();
#pragma unroll
        for (int m = 0; m < 8; m++) {
            int idx = tid + 256 * m;
            sh[idx >> 5][idx & 31] =
                h[(size_t)(row0 + (idx >> 5)) * FIN + k0 + (idx & 31)];
            sw[idx >> 6][idx & 63] = W[(size_t)(k0 + (idx >> 6)) * FO + (idx & 63)];
        }
        __syncthreads();
#pragma unroll
        for (int kk = 0; kk < 32; kk++) {
            float a[4];
#pragma unroll
            for (int i = 0; i < 4; i++) a[i] = sh[ty * 4 + i][kk];
            float4 bb = *(const float4*)&sw[kk][tx * 4];
#pragma unroll
            for (int i = 0; i < 4; i++) {
                acc[i][0] = fmaf(a[i], bb.x, acc[i][0]);
                acc[i][1] = fmaf(a[i], bb.y, acc[i][1]);
                acc[i][2] = fmaf(a[i], bb.z, acc[i][2]);
                acc[i][3] = fmaf(a[i], bb.w, acc[i][3]);
            }
        }
    }
#pragma unroll
    for (int i = 0; i < 4; i++) {
        *(float4*)&g_X[(size_t)(row0 + ty * 4 + i) * FO + tx * 4] =
            make_float4(acc[i][0], acc[i][1], acc[i][2], acc[i][3]);
#pragma unroll
        for (int j = 0; j < 4; j++) ts[ty * 4 + i][tx * 4 + j] = acc[i][j];
    }
    __syncthreads();

    const int n    = tid >> 2;
    const int part = tid & 3;
    const int b    = row0 >> 12;
    const int jloc = row0 & 4095;
    size_t base = ((size_t)(b * 64 + n) * Ndim + jloc + part * 16);
#pragma unroll
    for (int jj = 0; jj < 16; jj += 2) {
        float v0 = ts[part * 16 + jj][n];
        float v1 = ts[part * 16 + jj + 1][n];
        unsigned hpack = pack_f16x2(v0, v1);
        float r0f = v0 - f16lo_f(hpack);
        float r1f = v1 - f16hi_f(hpack);
        unsigned lpack = pack_f16x2(r0f, r1f);
        *(unsigned*)((char*)g_XTh + (base + jj) * 2) = hpack;
        *(unsigned*)((char*)g_XTl + (base + jj) * 2) = lpack;
    }
}

// ---------------- Kernel B: attention coefficients -> exp pairs ----------------
__global__ __launch_bounds__(128) void k_coef(const float* __restrict__ Wl,
                                              const float* __restrict__ Wr) {
    const int row  = blockIdx.x * 4 + (threadIdx.x >> 5);
    const int lane = threadIdx.x & 31;
    float2 x2 = *(const float2*)&g_X[(size_t)row * FO + lane * 2];
#pragma unroll
    for (int hh = 0; hh < NH; hh++) {
        float2 wl = *(const float2*)&Wl[hh * FO + lane * 2];
        float v = x2.x * wl.x + x2.y * wl.y;
#pragma unroll
        for (int o = 16; o > 0; o >>= 1) v += __shfl_xor_sync(0xffffffffu, v, o);
        float2 wr = *(const float2*)&Wr[hh * FO + lane * 2];
        float u = x2.x * wr.x + x2.y * wr.y;
#pragma unroll
        for (int o = 16; o > 0; o >>= 1) u += __shfl_xor_sync(0xffffffffu, u, o);
        if (lane == 0) {
            // 2^-12 scale folded here; cancels in softmax (den uses scaled p too)
            g_elEF[row * NH + hh] =
                make_float2(__expf(v) * PSCALE, __expf(0.2f * v) * PSCALE);
            g_erEF[row * NH + hh] = make_float2(__expf(u), __expf(0.2f * u));
        }
    }
}

// ---------------- Kernel D: pack adjacency to bitmasks ----------------
__global__ __launch_bounds__(256) void k_pack(const int* __restrict__ adj) {
    const int lane = threadIdx.x & 31;
    const int wgl  = (blockIdx.x * 8) + (threadIdx.x >> 5);
#pragma unroll 4
    for (int it = 0; it < 128; it++) {
        int word = wgl + it * 8192;
        int v = adj[(size_t)word * 32 + lane];
        unsigned m = __ballot_sync(0xffffffffu, v != 0);
        if (lane == 0) g_mask[word] = m;
    }
}

// ---------------- Kernel E: fused attention + PV (fp16 2-pass MMA) ----------
#define XS_STRIDE 144                  // 128B data + 16B pad per n-row
#define XS_BYTES  (64 * XS_STRIDE)     // 9216 per stage per array
#define ER_CNT    (NH * TJ)            // float2 entries per stage, [h][j]
__global__ __launch_bounds__(256, 2) void k_attn(const float* __restrict__ bias,
                                                 float* __restrict__ out) {
    __shared__ __align__(16) unsigned char sXh[2][XS_BYTES];
    __shared__ __align__(16) unsigned char sXl[2][XS_BYTES];
    __shared__ __align__(16) float2 erS[2][ER_CNT];

    const int tid  = threadIdx.x;
    const int w    = tid >> 5;
    const int lane = tid & 31;
    const int g    = lane >> 2;
    const int q    = lane & 3;
    const int q2   = q * 2;

    const int bb = blockIdx.x >> 7;
    const int i0 = (blockIdx.x & 127) * TI;
    const int hh = w >> 1;
    const int iA = i0 + (w & 1) * 16 + g;        // rows iA and iA+8

    const float2 efAf = g_elEF[((bb << 12) + iA) * NH + hh];
    const float2 efBf = g_elEF[((bb << 12) + iA + 8) * NH + hh];
    const unsigned long long efA64 = pk2(efAf.x, efAf.y);
    const unsigned long long efB64 = pk2(efBf.x, efBf.y);
    const uint2* mrowA = (const uint2*)&g_mask[(size_t)((bb << 12) + iA) * NT];
    const uint2* mrowB = (const uint2*)&g_mask[(size_t)((bb << 12) + iA + 8) * NT];

    float acc[8][4];
#pragma unroll
    for (int n = 0; n < 8; n++)
#pragma unroll
        for (int k = 0; k < 4; k++) acc[n][k] = 0.0f;
    float den0 = 0.0f, den1 = 0.0f;

    const char* XThB = (const char*)(g_XTh + (size_t)bb * 64 * Ndim);
    const char* XTlB = (const char*)(g_XTl + (size_t)bb * 64 * Ndim);
    const float2* erB = g_erEF + (size_t)(bb << 12) * NH;

    // staging mapping: X rows (feature n = tid>>2), 32B chunk sp = tid&3
    const int sn = tid >> 2;
    const int sp = tid & 3;
    const unsigned aXh = (unsigned)__cvta_generic_to_shared(&sXh[0][0]);
    const unsigned aXl = (unsigned)__cvta_generic_to_shared(&sXl[0][0]);
    const unsigned aEr = (unsigned)__cvta_generic_to_shared(&erS[0][0]);
    const unsigned dstOff = sn * XS_STRIDE + sp * 32;
    const size_t   srcOff = ((size_t)sn * Ndim + sp * 16) * 2;   // bytes, + j0*2
    // er staging: thread -> (j = tid>>2, h = tid&3); dst [h][j]
    const unsigned erDst  = ((sp) * TJ + sn) * 8;
    const size_t   erSrc  = ((size_t)sn * NH + sp) * 8;          // bytes, + j0*NH*8
    // ldmatrix lane base: row (lane&7), 16B chunk (lane>>3)
    const unsigned lb = (lane & 7) * XS_STRIDE + (lane >> 3) * 16;

    // prologue: stage tile 0
    {
        cp16(aXh + dstOff,      XThB + srcOff);
        cp16(aXh + dstOff + 16, XThB + srcOff + 16);
        cp16(aXl + dstOff,      XTlB + srcOff);
        cp16(aXl + dstOff + 16, XTlB + srcOff + 16);
        cp8(aEr + erDst, (const char*)erB + erSrc);
        cp_commit();
    }

    uint2 mwA = mrowA[0];
    uint2 mwB = mrowB[0];

    for (int jt = 0; jt < NJT; jt++) {
        const int st = jt & 1;
        cp_wait0();
        __syncthreads();

        if (jt + 1 < NJT) {
            const size_t jb = (size_t)(jt + 1) * TJ * 2;       // bytes along j
            const unsigned so = (st ^ 1) * XS_BYTES + dstOff;
            cp16(aXh + so,      XThB + srcOff + jb);
            cp16(aXh + so + 16, XThB + srcOff + jb + 16);
            cp16(aXl + so,      XTlB + srcOff + jb);
            cp16(aXl + so + 16, XTlB + srcOff + jb + 16);
            cp8(aEr + (st ^ 1) * (ER_CNT * 8) + erDst,
                (const char*)erB + erSrc + (size_t)(jt + 1) * TJ * NH * 8);
        }
        cp_commit();

        uint2 nmwA = make_uint2(0, 0), nmwB = make_uint2(0, 0);
        if (jt + 1 < NJT) { nmwA = mrowA[jt + 1]; nmwB = mrowB[jt + 1]; }

        const unsigned long long* erU =
            (const unsigned long long*)(erS[st] + hh * TJ);
        const unsigned xhB = aXh + st * XS_BYTES + lb;
        const unsigned xlB = aXl + st * XS_BYTES + lb;

#pragma unroll
        for (int ktp = 0; ktp < 2; ktp++) {
            const unsigned wA = ktp ? mwA.y : mwA.x;
            const unsigned wB = ktp ? mwB.y : mwB.x;

            unsigned aP[2][4];    // fp16x2 A fragments, s = 0,1 (two k16 chunks)
#pragma unroll
            for (int s = 0; s < 2; s++) {
                const int cb = ktp * 32 + s * 16 + q2;
                unsigned long long e0 = erU[cb];
                unsigned long long e1 = erU[cb + 1];
                unsigned long long e2 = erU[cb + 8];
                unsigned long long e3 = erU[cb + 9];

                unsigned msA = wA >> (s * 16 + q2);
                unsigned msB = wB >> (s * 16 + q2);

                float2 fA0 = upk2(mul2(efA64, e0));
                float2 fA1 = upk2(mul2(efA64, e1));
                float2 fA2 = upk2(mul2(efA64, e2));
                float2 fA3 = upk2(mul2(efA64, e3));
                float2 fB0 = upk2(mul2(efB64, e0));
                float2 fB1 = upk2(mul2(efB64, e1));
                float2 fB2 = upk2(mul2(efB64, e2));
                float2 fB3 = upk2(mul2(efB64, e3));

                float pA0 = (msA & 1u)   ? fmaxf(fA0.x, fA0.y) : 0.0f;
                float pA1 = (msA & 2u)   ? fmaxf(fA1.x, fA1.y) : 0.0f;
                float pA2 = (msA & 256u) ? fmaxf(fA2.x, fA2.y) : 0.0f;
                float pA3 = (msA & 512u) ? fmaxf(fA3.x, fA3.y) : 0.0f;
                float pB0 = (msB & 1u)   ? fmaxf(fB0.x, fB0.y) : 0.0f;
                float pB1 = (msB & 2u)   ? fmaxf(fB1.x, fB1.y) : 0.0f;
                float pB2 = (msB & 256u) ? fmaxf(fB2.x, fB2.y) : 0.0f;
                float pB3 = (msB & 512u) ? fmaxf(fB3.x, fB3.y) : 0.0f;

                den0 += (pA0 + pA1) + (pA2 + pA3);
                den1 += (pB0 + pB1) + (pB2 + pB3);

                aP[s][0] = pack_f16x2(pA0, pA1);
                aP[s][1] = pack_f16x2(pB0, pB1);
                aP[s][2] = pack_f16x2(pA2, pA3);
                aP[s][3] = pack_f16x2(pB2, pB3);
            }

            const unsigned kb = ktp * 64;   // byte offset of this kt-pair along j
#pragma unroll
            for (int nt = 0; nt < 8; nt++) {
                const unsigned ro = nt * (8 * XS_STRIDE) + kb;
                unsigned bh0, bh1, bh2, bh3, bl0, bl1, bl2, bl3;
                ldsm4(bh0, bh1, bh2, bh3, xhB + ro);
                ldsm4(bl0, bl1, bl2, bl3, xlB + ro);
                mma_f16(acc[nt], aP[0], bh0, bh1);
                mma_f16(acc[nt], aP[0], bl0, bl1);
                mma_f16(acc[nt], aP[1], bh2, bh3);
                mma_f16(acc[nt], aP[1], bl2, bl3);
            }
        }
        mwA = nmwA;
        mwB = nmwB;
    }

    // reduce denominators across the 4 lanes of each row group
    den0 += __shfl_xor_sync(0xffffffffu, den0, 1);
    den0 += __shfl_xor_sync(0xffffffffu, den0, 2);
    den1 += __shfl_xor_sync(0xffffffffu, den1, 1);
    den1 += __shfl_xor_sync(0xffffffffu, den1, 2);
    const float inv0 = 1.0f / den0;
    const float inv1 = 1.0f / den1;

    float* o0 = out + (size_t)((bb << 12) + iA) * (NH * FO) + hh * FO;
    float* o1 = o0 + (size_t)8 * (NH * FO);
#pragma unroll
    for (int nt = 0; nt < 8; nt++) {
        const int col = nt * 8 + q2;
        float2 bv = *(const float2*)&bias[hh * FO + col];
        float v00 = fmaf(acc[nt][0], inv0, bv.x);
        float v01 = fmaf(acc[nt][1], inv0, bv.y);
        float v10 = fmaf(acc[nt][2], inv1, bv.x);
        float v11 = fmaf(acc[nt][3], inv1, bv.y);
        v00 = v00 > 0.0f ? v00 : expm1f(v00);
        v01 = v01 > 0.0f ? v01 : expm1f(v01);
        v10 = v10 > 0.0f ? v10 : expm1f(v10);
        v11 = v11 > 0.0f ? v11 : expm1f(v11);
        *(float2*)&o0[col] = make_float2(v00, v01);
        *(float2*)&o1[col] = make_float2(v10, v11);
    }
}

// ---------------- launch ----------------
extern "C" void kernel_launch(void* const* d_in, const int* in_sizes, int n_in,
                              void* d_out, int out_size) {
    const int*   adj = (const int*)  d_in[0];  // (B,N,N) int32
    const float* h   = (const float*)d_in[1];  // (B,N,256)
    const float* W   = (const float*)d_in[2];  // (256,64)
    const float* Wl  = (const float*)d_in[3];  // (4,64)
    const float* Wr  = (const float*)d_in[4];  // (4,64)
    const float* bia = (const float*)d_in[5];  // (64,)
    float* out = (float*)d_out;                // (B,N,256)

    k_pack<<<1024, 256>>>(adj);
    k_gemm_xw<<<ROWS / 64, 256>>>(h, W);
    k_coef<<<ROWS / 4, 128>>>(Wl, Wr);
    k_attn<<<Bdim * (Ndim / TI), 256>>>(bia, out);
}

// round 14
// speedup vs baseline: 1.9190x; 1.3890x over previous
#include <cuda_runtime.h>
#include <cuda_fp16.h>

// Problem constants (fixed by the reference)
#define Bdim 2
#define Ndim 4096
#define FIN  256
#define FO   64
#define NH   4
#define ROWS (Bdim * Ndim)   // 8192

#define TI 32               // i-rows per block
#define TJ 64               // j-cols per tile
#define NJT (Ndim / TJ)     // 64 j-tiles
#define NT (Ndim / 32)      // 128 mask words per row

#define PSCALE 2.44140625e-4f   // 2^-12, folded into elEF; cancels in softmax

// -------- device scratch (no allocation allowed) --------
__device__ float  g_X   [ROWS * FO];          // (B,N,64) = h @ W
__device__ float2 g_elEF[ROWS * NH];          // {exp(el), exp(0.2*el)} * 2^-12
__device__ float2 g_erEF[ROWS * NH];          // {exp(er), exp(0.2*er)}  (j,h) contiguous
__device__ __half g_XTh[ROWS * FO];           // X^T fp16, [b][n(64)][j(4096)]
__device__ unsigned g_mask[ROWS * NT];        // adjacency bitmask [row][jword]

// -------- helpers --------
__device__ __forceinline__ unsigned pack_f16x2(float lo, float hi) {
    unsigned r;
    asm("cvt.rn.f16x2.f32 %0, %1, %2;" : "=r"(r) : "f"(hi), "f"(lo));
    return r;
}

__device__ __forceinline__ unsigned long long pk2(float a, float b) {
    unsigned long long r;
    asm("mov.b64 %0, {%1, %2};"
        : "=l"(r) : "r"(__float_as_uint(a)), "r"(__float_as_uint(b)));
    return r;
}
__device__ __forceinline__ float2 upk2(unsigned long long v) {
    unsigned int lo, hi;
    asm("mov.b64 {%0, %1}, %2;" : "=r"(lo), "=r"(hi) : "l"(v));
    return make_float2(__uint_as_float(lo), __uint_as_float(hi));
}
__device__ __forceinline__ unsigned long long mul2(unsigned long long a,
                                                   unsigned long long b) {
    unsigned long long d;
    asm("mul.rn.f32x2 %0, %1, %2;" : "=l"(d) : "l"(a), "l"(b));
    return d;
}

__device__ __forceinline__ void mma_f16(float* c, const unsigned* a,
                                        unsigned b0, unsigned b1) {
    asm volatile(
        "mma.sync.aligned.m16n8k16.row.col.f32.f16.f16.f32 "
        "{%0,%1,%2,%3}, {%4,%5,%6,%7}, {%8,%9}, {%0,%1,%2,%3};"
        : "+f"(c[0]), "+f"(c[1]), "+f"(c[2]), "+f"(c[3])
        : "r"(a[0]), "r"(a[1]), "r"(a[2]), "r"(a[3]), "r"(b0), "r"(b1));
}
__device__ __forceinline__ void ldsm4(unsigned& r0, unsigned& r1,
                                      unsigned& r2, unsigned& r3, unsigned addr) {
    asm volatile("ldmatrix.sync.aligned.m8n8.x4.shared.b16 {%0,%1,%2,%3}, [%4];"
                 : "=r"(r0), "=r"(r1), "=r"(r2), "=r"(r3) : "r"(addr));
}
__device__ __forceinline__ void cp16(unsigned saddr, const void* g) {
    asm volatile("cp.async.cg.shared.global [%0], [%1], 16;\n" :: "r"(saddr), "l"(g));
}
__device__ __forceinline__ void cp8(unsigned saddr, const void* g) {
    asm volatile("cp.async.ca.shared.global [%0], [%1], 8;\n" :: "r"(saddr), "l"(g));
}
__device__ __forceinline__ void cp_commit() { asm volatile("cp.async.commit_group;\n" ::); }
__device__ __forceinline__ void cp_wait0()  { asm volatile("cp.async.wait_group 0;\n" ::); }

// ---------------- Kernel A: X = h @ W, fused transpose + fp16 cast ----------
__global__ __launch_bounds__(256) void k_gemm_xw(const float* __restrict__ h,
                                                 const float* __restrict__ W) {
    __shared__ float sh[64][33];
    __shared__ float sw[32][64];
    __shared__ float ts[64][65];   // staging tile [row_local][feature]

    const int tid  = threadIdx.x;
    const int tx   = tid & 15;
    const int ty   = tid >> 4;
    const int row0 = blockIdx.x * 64;

    float acc[4][4];
#pragma unroll
    for (int i = 0; i < 4; i++)
#pragma unroll
        for (int j = 0; j < 4; j++) acc[i][j] = 0.0f;

    for (int k0 = 0; k0 < FIN; k0 += 32) {
        __syncthreads();
#pragma unroll
        for (int m = 0; m < 8; m++) {
            int idx = tid + 256 * m;
            sh[idx >> 5][idx & 31] =
                h[(size_t)(row0 + (idx >> 5)) * FIN + k0 + (idx & 31)];
            sw[idx >> 6][idx & 63] = W[(size_t)(k0 + (idx >> 6)) * FO + (idx & 63)];
        }
        __syncthreads();
#pragma unroll
        for (int kk = 0; kk < 32; kk++) {
            float a[4];
#pragma unroll
            for (int i = 0; i < 4; i++) a[i] = sh[ty * 4 + i][kk];
            float4 bb = *(const float4*)&sw[kk][tx * 4];
#pragma unroll
            for (int i = 0; i < 4; i++) {
                acc[i][0] = fmaf(a[i], bb.x, acc[i][0]);
                acc[i][1] = fmaf(a[i], bb.y, acc[i][1]);
                acc[i][2] = fmaf(a[i], bb.z, acc[i][2]);
                acc[i][3] = fmaf(a[i], bb.w, acc[i][3]);
            }
        }
    }
#pragma unroll
    for (int i = 0; i < 4; i++) {
        *(float4*)&g_X[(size_t)(row0 + ty * 4 + i) * FO + tx * 4] =
            make_float4(acc[i][0], acc[i][1], acc[i][2], acc[i][3]);
#pragma unroll
        for (int j = 0; j < 4; j++) ts[ty * 4 + i][tx * 4 + j] = acc[i][j];
    }
    __syncthreads();

    const int n    = tid >> 2;
    const int part = tid & 3;
    const int b    = row0 >> 12;
    const int jloc = row0 & 4095;
    size_t base = ((size_t)(b * 64 + n) * Ndim + jloc + part * 16);
#pragma unroll
    for (int jj = 0; jj < 16; jj += 2) {
        float v0 = ts[part * 16 + jj][n];
        float v1 = ts[part * 16 + jj + 1][n];
        *(unsigned*)((char*)g_XTh + (base + jj) * 2) = pack_f16x2(v0, v1);
    }
}

// ---------------- Kernel B: attention coefficients -> exp pairs ----------------
__global__ __launch_bounds__(128) void k_coef(const float* __restrict__ Wl,
                                              const float* __restrict__ Wr) {
    const int row  = blockIdx.x * 4 + (threadIdx.x >> 5);
    const int lane = threadIdx.x & 31;
    float2 x2 = *(const float2*)&g_X[(size_t)row * FO + lane * 2];
#pragma unroll
    for (int hh = 0; hh < NH; hh++) {
        float2 wl = *(const float2*)&Wl[hh * FO + lane * 2];
        float v = x2.x * wl.x + x2.y * wl.y;
#pragma unroll
        for (int o = 16; o > 0; o >>= 1) v += __shfl_xor_sync(0xffffffffu, v, o);
        float2 wr = *(const float2*)&Wr[hh * FO + lane * 2];
        float u = x2.x * wr.x + x2.y * wr.y;
#pragma unroll
        for (int o = 16; o > 0; o >>= 1) u += __shfl_xor_sync(0xffffffffu, u, o);
        if (lane == 0) {
            // 2^-12 scale folded here; cancels in softmax (den uses scaled p too)
            g_elEF[row * NH + hh] =
                make_float2(__expf(v) * PSCALE, __expf(0.2f * v) * PSCALE);
            g_erEF[row * NH + hh] = make_float2(__expf(u), __expf(0.2f * u));
        }
    }
}

// ---------------- Kernel D: pack adjacency to bitmasks ----------------
__global__ __launch_bounds__(256) void k_pack(const int* __restrict__ adj) {
    const int lane = threadIdx.x & 31;
    const int wgl  = (blockIdx.x * 8) + (threadIdx.x >> 5);
#pragma unroll 4
    for (int it = 0; it < 128; it++) {
        int word = wgl + it * 8192;
        int v = adj[(size_t)word * 32 + lane];
        unsigned m = __ballot_sync(0xffffffffu, v != 0);
        if (lane == 0) g_mask[word] = m;
    }
}

// ---------------- Kernel E: fused attention + PV (fp16 1-pass MMA) ----------
#define XS_STRIDE 144                  // 128B data + 16B pad per n-row
#define XS_BYTES  (64 * XS_STRIDE)     // 9216 per stage
#define ER_CNT    (NH * TJ)            // float2 entries per stage, [h][j]
__global__ __launch_bounds__(256, 2) void k_attn(const float* __restrict__ bias,
                                                 float* __restrict__ out) {
    __shared__ __align__(16) unsigned char sXh[2][XS_BYTES];
    __shared__ __align__(16) float2 erS[2][ER_CNT];

    const int tid  = threadIdx.x;
    const int w    = tid >> 5;
    const int lane = tid & 31;
    const int g    = lane >> 2;
    const int q    = lane & 3;
    const int q2   = q * 2;

    const int bb = blockIdx.x >> 7;
    const int i0 = (blockIdx.x & 127) * TI;
    const int hh = w >> 1;
    const int iA = i0 + (w & 1) * 16 + g;        // rows iA and iA+8

    const float2 efAf = g_elEF[((bb << 12) + iA) * NH + hh];
    const float2 efBf = g_elEF[((bb << 12) + iA + 8) * NH + hh];
    const unsigned long long efA64 = pk2(efAf.x, efAf.y);
    const unsigned long long efB64 = pk2(efBf.x, efBf.y);
    const uint2* mrowA = (const uint2*)&g_mask[(size_t)((bb << 12) + iA) * NT];
    const uint2* mrowB = (const uint2*)&g_mask[(size_t)((bb << 12) + iA + 8) * NT];

    float acc[8][4];
#pragma unroll
    for (int n = 0; n < 8; n++)
#pragma unroll
        for (int k = 0; k < 4; k++) acc[n][k] = 0.0f;
    float den0 = 0.0f, den1 = 0.0f;

    const char* XThB = (const char*)(g_XTh + (size_t)bb * 64 * Ndim);
    const float2* erB = g_erEF + (size_t)(bb << 12) * NH;

    // staging mapping: X rows (feature n = tid>>2), 32B chunk sp = tid&3
    const int sn = tid >> 2;
    const int sp = tid & 3;
    const unsigned aXh = (unsigned)__cvta_generic_to_shared(&sXh[0][0]);
    const unsigned aEr = (unsigned)__cvta_generic_to_shared(&erS[0][0]);
    const unsigned dstOff = sn * XS_STRIDE + sp * 32;
    const size_t   srcOff = ((size_t)sn * Ndim + sp * 16) * 2;   // bytes, + j0*2
    // er staging: thread -> (j = tid>>2, h = tid&3); dst [h][j]
    const unsigned erDst  = ((sp) * TJ + sn) * 8;
    const size_t   erSrc  = ((size_t)sn * NH + sp) * 8;          // bytes, + j0*NH*8
    // ldmatrix lane base: row (lane&7), 16B chunk (lane>>3)
    const unsigned lb = (lane & 7) * XS_STRIDE + (lane >> 3) * 16;

    // prologue: stage tile 0
    {
        cp16(aXh + dstOff,      XThB + srcOff);
        cp16(aXh + dstOff + 16, XThB + srcOff + 16);
        cp8(aEr + erDst, (const char*)erB + erSrc);
        cp_commit();
    }

    uint2 mwA = mrowA[0];
    uint2 mwB = mrowB[0];

    for (int jt = 0; jt < NJT; jt++) {
        const int st = jt & 1;
        cp_wait0();
        __syncthreads();

        if (jt + 1 < NJT) {
            const size_t jb = (size_t)(jt + 1) * TJ * 2;       // bytes along j
            const unsigned so = (st ^ 1) * XS_BYTES + dstOff;
            cp16(aXh + so,      XThB + srcOff + jb);
            cp16(aXh + so + 16, XThB + srcOff + jb + 16);
            cp8(aEr + (st ^ 1) * (ER_CNT * 8) + erDst,
                (const char*)erB + erSrc + (size_t)(jt + 1) * TJ * NH * 8);
        }
        cp_commit();

        uint2 nmwA = make_uint2(0, 0), nmwB = make_uint2(0, 0);
        if (jt + 1 < NJT) { nmwA = mrowA[jt + 1]; nmwB = mrowB[jt + 1]; }

        const unsigned long long* erU =
            (const unsigned long long*)(erS[st] + hh * TJ);
        const unsigned xhB = aXh + st * XS_BYTES + lb;

#pragma unroll
        for (int ktp = 0; ktp < 2; ktp++) {
            const unsigned wA = ktp ? mwA.y : mwA.x;
            const unsigned wB = ktp ? mwB.y : mwB.x;

            unsigned aP[2][4];    // fp16x2 A fragments, s = 0,1 (two k16 chunks)
#pragma unroll
            for (int s = 0; s < 2; s++) {
                const int cb = ktp * 32 + s * 16 + q2;
                unsigned long long e0 = erU[cb];
                unsigned long long e1 = erU[cb + 1];
                unsigned long long e2 = erU[cb + 8];
                unsigned long long e3 = erU[cb + 9];

                unsigned msA = wA >> (s * 16 + q2);
                unsigned msB = wB >> (s * 16 + q2);

                float2 fA0 = upk2(mul2(efA64, e0));
                float2 fA1 = upk2(mul2(efA64, e1));
                float2 fA2 = upk2(mul2(efA64, e2));
                float2 fA3 = upk2(mul2(efA64, e3));
                float2 fB0 = upk2(mul2(efB64, e0));
                float2 fB1 = upk2(mul2(efB64, e1));
                float2 fB2 = upk2(mul2(efB64, e2));
                float2 fB3 = upk2(mul2(efB64, e3));

                float pA0 = (msA & 1u)   ? fmaxf(fA0.x, fA0.y) : 0.0f;
                float pA1 = (msA & 2u)   ? fmaxf(fA1.x, fA1.y) : 0.0f;
                float pA2 = (msA & 256u) ? fmaxf(fA2.x, fA2.y) : 0.0f;
                float pA3 = (msA & 512u) ? fmaxf(fA3.x, fA3.y) : 0.0f;
                float pB0 = (msB & 1u)   ? fmaxf(fB0.x, fB0.y) : 0.0f;
                float pB1 = (msB & 2u)   ? fmaxf(fB1.x, fB1.y) : 0.0f;
                float pB2 = (msB & 256u) ? fmaxf(fB2.x, fB2.y) : 0.0f;
                float pB3 = (msB & 512u) ? fmaxf(fB3.x, fB3.y) : 0.0f;

                den0 += (pA0 + pA1) + (pA2 + pA3);
                den1 += (pB0 + pB1) + (pB2 + pB3);

                aP[s][0] = pack_f16x2(pA0, pA1);
                aP[s][1] = pack_f16x2(pB0, pB1);
                aP[s][2] = pack_f16x2(pA2, pA3);
                aP[s][3] = pack_f16x2(pB2, pB3);
            }

            const unsigned kb = ktp * 64;   // byte offset of this kt-pair along j
#pragma unroll
            for (int nt = 0; nt < 8; nt++) {
                const unsigned ro = nt * (8 * XS_STRIDE) + kb;
                unsigned bh0, bh1, bh2, bh3;
                ldsm4(bh0, bh1, bh2, bh3, xhB + ro);
                mma_f16(acc[nt], aP[0], bh0, bh1);
                mma_f16(acc[nt], aP[1], bh2, bh3);
            }
        }
        mwA = nmwA;
        mwB = nmwB;
    }

    // reduce denominators across the 4 lanes of each row group
    den0 += __shfl_xor_sync(0xffffffffu, den0, 1);
    den0 += __shfl_xor_sync(0xffffffffu, den0, 2);
    den1 += __shfl_xor_sync(0xffffffffu, den1, 1);
    den1 += __shfl_xor_sync(0xffffffffu, den1, 2);
    const float inv0 = 1.0f / den0;
    const float inv1 = 1.0f / den1;

    float* o0 = out + (size_t)((bb << 12) + iA) * (NH * FO) + hh * FO;
    float* o1 = o0 + (size_t)8 * (NH * FO);
#pragma unroll
    for (int nt = 0; nt < 8; nt++) {
        const int col = nt * 8 + q2;
        float2 bv = *(const float2*)&bias[hh * FO + col];
        float v00 = fmaf(acc[nt][0], inv0, bv.x);
        float v01 = fmaf(acc[nt][1], inv0, bv.y);
        float v10 = fmaf(acc[nt][2], inv1, bv.x);
        float v11 = fmaf(acc[nt][3], inv1, bv.y);
        v00 = v00 > 0.0f ? v00 : expm1f(v00);
        v01 = v01 > 0.0f ? v01 : expm1f(v01);
        v10 = v10 > 0.0f ? v10 : expm1f(v10);
        v11 = v11 > 0.0f ? v11 : expm1f(v11);
        *(float2*)&o0[col] = make_float2(v00, v01);
        *(float2*)&o1[col] = make_float2(v10, v11);
    }
}

// ---------------- launch ----------------
extern "C" void kernel_launch(void* const* d_in, const int* in_sizes, int n_in,
                              void* d_out, int out_size) {
    const int*   adj = (const int*)  d_in[0];  // (B,N,N) int32
    const float* h   = (const float*)d_in[1];  // (B,N,256)
    const float* W   = (const float*)d_in[2];  // (256,64)
    const float* Wl  = (const float*)d_in[3];  // (4,64)
    const float* Wr  = (const float*)d_in[4];  // (4,64)
    const float* bia = (const float*)d_in[5];  // (64,)
    float* out = (float*)d_out;                // (B,N,256)

    k_pack<<<1024, 256>>>(adj);
    k_gemm_xw<<<ROWS / 64, 256>>>(h, W);
    k_coef<<<ROWS / 4, 128>>>(Wl, Wr);
    k_attn<<<Bdim * (Ndim / TI), 256>>>(bia, out);
}

// round 16
// speedup vs baseline: 2.0449x; 1.0656x over previous
#include <cuda_runtime.h>
#include <cuda_fp16.h>

// Problem constants (fixed by the reference)
#define Bdim 2
#define Ndim 4096
#define FIN  256
#define FO   64
#define NH   4
#define ROWS (Bdim * Ndim)   // 8192

#define TI 32               // i-rows per block
#define TJ 64               // j-cols per tile
#define NJT (Ndim / TJ)     // 64 j-tiles
#define NT (Ndim / 32)      // 128 mask words per row

#define PSCALE 2.44140625e-4f   // 2^-12, folded into elEF; cancels in softmax
#define ONES16x2 0x3C003C00u    // fp16 {1.0, 1.0}

typedef unsigned long long ull;

// -------- device scratch (no allocation allowed) --------
__device__ float  g_X   [ROWS * FO];          // (B,N,64) = h @ W
__device__ float2 g_elEF[ROWS * NH];          // {exp(el), exp(0.2*el)} * 2^-12
__device__ float  g_erE [Bdim * NH * Ndim];   // exp(er),     [b][h][j]
__device__ float  g_erF [Bdim * NH * Ndim];   // exp(0.2*er), [b][h][j]
__device__ __half g_XTh[ROWS * FO];           // X^T fp16, [b][n(64)][j(4096)]
__device__ unsigned g_mask[ROWS * NT];        // adjacency bitmask [row][jword]

// -------- helpers --------
__device__ __forceinline__ unsigned pack_f16x2(float lo, float hi) {
    unsigned r;
    asm("cvt.rn.f16x2.f32 %0, %1, %2;" : "=r"(r) : "f"(hi), "f"(lo));
    return r;
}
__device__ __forceinline__ ull pk2(float a, float b) {
    ull r;
    asm("mov.b64 %0, {%1, %2};"
        : "=l"(r) : "r"(__float_as_uint(a)), "r"(__float_as_uint(b)));
    return r;
}
__device__ __forceinline__ float2 upk2(ull v) {
    unsigned lo, hi;
    asm("mov.b64 {%0, %1}, %2;" : "=r"(lo), "=r"(hi) : "l"(v));
    return make_float2(__uint_as_float(lo), __uint_as_float(hi));
}
__device__ __forceinline__ ull mul2(ull a, ull b) {
    ull d;
    asm("mul.rn.f32x2 %0, %1, %2;" : "=l"(d) : "l"(a), "l"(b));
    return d;
}
// packed two-regime max: unpack + 2x FMNMX (max.f32x2 not supported by ptxas)
__device__ __forceinline__ float2 max2f(ull a, ull b) {
    float2 x = upk2(a), y = upk2(b);
    return make_float2(fmaxf(x.x, y.x), fmaxf(x.y, y.y));
}

__device__ __forceinline__ void mma_f16(float* c, const unsigned* a,
                                        unsigned b0, unsigned b1) {
    asm volatile(
        "mma.sync.aligned.m16n8k16.row.col.f32.f16.f16.f32 "
        "{%0,%1,%2,%3}, {%4,%5,%6,%7}, {%8,%9}, {%0,%1,%2,%3};"
        : "+f"(c[0]), "+f"(c[1]), "+f"(c[2]), "+f"(c[3])
        : "r"(a[0]), "r"(a[1]), "r"(a[2]), "r"(a[3]), "r"(b0), "r"(b1));
}
__device__ __forceinline__ void ldsm4(unsigned& r0, unsigned& r1,
                                      unsigned& r2, unsigned& r3, unsigned addr) {
    asm volatile("ldmatrix.sync.aligned.m8n8.x4.shared.b16 {%0,%1,%2,%3}, [%4];"
                 : "=r"(r0), "=r"(r1), "=r"(r2), "=r"(r3) : "r"(addr));
}
__device__ __forceinline__ void cp16(unsigned saddr, const void* g) {
    asm volatile("cp.async.cg.shared.global [%0], [%1], 16;\n" :: "r"(saddr), "l"(g));
}
__device__ __forceinline__ void cp_commit() { asm volatile("cp.async.commit_group;\n" ::); }
__device__ __forceinline__ void cp_wait0()  { asm volatile("cp.async.wait_group 0;\n" ::); }

// ---------------- Kernel A: X = h @ W, fused transpose + fp16 cast ----------
__global__ __launch_bounds__(256) void k_gemm_xw(const float* __restrict__ h,
                                                 const float* __restrict__ W) {
    __shared__ float sh[64][33];
    __shared__ float sw[32][64];
    __shared__ float ts[64][65];   // staging tile [row_local][feature]

    const int tid  = threadIdx.x;
    const int tx   = tid & 15;
    const int ty   = tid >> 4;
    const int row0 = blockIdx.x * 64;

    float acc[4][4];
#pragma unroll
    for (int i = 0; i < 4; i++)
#pragma unroll
        for (int j = 0; j < 4; j++) acc[i][j] = 0.0f;

    for (int k0 = 0; k0 < FIN; k0 += 32) {
        __syncthreads();
#pragma unroll
        for (int m = 0; m < 8; m++) {
            int idx = tid + 256 * m;
            sh[idx >> 5][idx & 31] =
                h[(size_t)(row0 + (idx >> 5)) * FIN + k0 + (idx & 31)];
            sw[idx >> 6][idx & 63] = W[(size_t)(k0 + (idx >> 6)) * FO + (idx & 63)];
        }
        __syncthreads();
#pragma unroll
        for (int kk = 0; kk < 32; kk++) {
            float a[4];
#pragma unroll
            for (int i = 0; i < 4; i++) a[i] = sh[ty * 4 + i][kk];
            float4 bb = *(const float4*)&sw[kk][tx * 4];
#pragma unroll
            for (int i = 0; i < 4; i++) {
                acc[i][0] = fmaf(a[i], bb.x, acc[i][0]);
                acc[i][1] = fmaf(a[i], bb.y, acc[i][1]);
                acc[i][2] = fmaf(a[i], bb.z, acc[i][2]);
                acc[i][3] = fmaf(a[i], bb.w, acc[i][3]);
            }
        }
    }
#pragma unroll
    for (int i = 0; i < 4; i++) {
        *(float4*)&g_X[(size_t)(row0 + ty * 4 + i) * FO + tx * 4] =
            make_float4(acc[i][0], acc[i][1], acc[i][2], acc[i][3]);
#pragma unroll
        for (int j = 0; j < 4; j++) ts[ty * 4 + i][tx * 4 + j] = acc[i][j];
    }
    __syncthreads();

    const int n    = tid >> 2;
    const int part = tid & 3;
    const int b    = row0 >> 12;
    const int jloc = row0 & 4095;
    size_t base = ((size_t)(b * 64 + n) * Ndim + jloc + part * 16);
#pragma unroll
    for (int jj = 0; jj < 16; jj += 2) {
        float v0 = ts[part * 16 + jj][n];
        float v1 = ts[part * 16 + jj + 1][n];
        *(unsigned*)((char*)g_XTh + (base + jj) * 2) = pack_f16x2(v0, v1);
    }
}

// ---------------- Kernel B: attention coefficients -> exp factors ------------
__global__ __launch_bounds__(128) void k_coef(const float* __restrict__ Wl,
                                              const float* __restrict__ Wr) {
    const int row  = blockIdx.x * 4 + (threadIdx.x >> 5);
    const int lane = threadIdx.x & 31;
    const int b    = row >> 12;
    const int jl   = row & 4095;
    float2 x2 = *(const float2*)&g_X[(size_t)row * FO + lane * 2];
#pragma unroll
    for (int hh = 0; hh < NH; hh++) {
        float2 wl = *(const float2*)&Wl[hh * FO + lane * 2];
        float v = x2.x * wl.x + x2.y * wl.y;
#pragma unroll
        for (int o = 16; o > 0; o >>= 1) v += __shfl_xor_sync(0xffffffffu, v, o);
        float2 wr = *(const float2*)&Wr[hh * FO + lane * 2];
        float u = x2.x * wr.x + x2.y * wr.y;
#pragma unroll
        for (int o = 16; o > 0; o >>= 1) u += __shfl_xor_sync(0xffffffffu, u, o);
        if (lane == 0) {
            // 2^-12 scale folded into el side; cancels in softmax
            g_elEF[row * NH + hh] =
                make_float2(__expf(v) * PSCALE, __expf(0.2f * v) * PSCALE);
            g_erE[(size_t)(b * NH + hh) * Ndim + jl] = __expf(u);
            g_erF[(size_t)(b * NH + hh) * Ndim + jl] = __expf(0.2f * u);
        }
    }
}

// ---------------- Kernel D: pack adjacency to bitmasks ----------------
__global__ __launch_bounds__(256) void k_pack(const int* __restrict__ adj) {
    const int lane = threadIdx.x & 31;
    const int wgl  = (blockIdx.x * 8) + (threadIdx.x >> 5);
#pragma unroll 4
    for (int it = 0; it < 128; it++) {
        int word = wgl + it * 8192;
        int v = adj[(size_t)word * 32 + lane];
        unsigned m = __ballot_sync(0xffffffffu, v != 0);
        if (lane == 0) g_mask[word] = m;
    }
}

// ---------------- Kernel E: fused attention + PV (fp16 MMA, den via ones-MMA) --
#define XS_STRIDE 144                  // 128B data + 16B pad per n-row
#define XS_BYTES  (64 * XS_STRIDE)     // 9216 per stage
#define ER_BYTES  (NH * TJ * 4)        // 1024 per stage per array
__global__ __launch_bounds__(256, 2) void k_attn(const float* __restrict__ bias,
                                                 float* __restrict__ out) {
    __shared__ __align__(16) unsigned char sXh[2][XS_BYTES];
    __shared__ __align__(16) float sEE[2][NH * TJ];   // exp(er),    [h][j]
    __shared__ __align__(16) float sEF[2][NH * TJ];   // exp(0.2er), [h][j]

    const int tid  = threadIdx.x;
    const int w    = tid >> 5;
    const int lane = tid & 31;
    const int g    = lane >> 2;
    const int q    = lane & 3;
    const int q2   = q * 2;

    const int bb = blockIdx.x >> 7;
    const int i0 = (blockIdx.x & 127) * TI;
    const int hh = w >> 1;
    const int iA = i0 + (w & 1) * 16 + g;        // rows iA and iA+8

    const float2 efAf = g_elEF[((bb << 12) + iA) * NH + hh];
    const float2 efBf = g_elEF[((bb << 12) + iA + 8) * NH + hh];
    const ull efAE = pk2(efAf.x, efAf.x);
    const ull efAF = pk2(efAf.y, efAf.y);
    const ull efBE = pk2(efBf.x, efBf.x);
    const ull efBF = pk2(efBf.y, efBf.y);
    const uint2* mrowA = (const uint2*)&g_mask[(size_t)((bb << 12) + iA) * NT];
    const uint2* mrowB = (const uint2*)&g_mask[(size_t)((bb << 12) + iA + 8) * NT];

    float acc[8][4];
#pragma unroll
    for (int n = 0; n < 8; n++)
#pragma unroll
        for (int k = 0; k < 4; k++) acc[n][k] = 0.0f;
    float accD[4] = {0.0f, 0.0f, 0.0f, 0.0f};    // den via ones-MMA

    const char* XThB = (const char*)(g_XTh + (size_t)bb * 64 * Ndim);

    // staging mapping: X rows (feature n = tid>>2), 32B chunk sp = tid&3
    const int sn = tid >> 2;
    const int sp = tid & 3;
    const unsigned aXh = (unsigned)__cvta_generic_to_shared(&sXh[0][0]);
    const unsigned aEE = (unsigned)__cvta_generic_to_shared(&sEE[0][0]);
    const unsigned aEF = (unsigned)__cvta_generic_to_shared(&sEF[0][0]);
    const unsigned dstOff = sn * XS_STRIDE + sp * 32;
    const size_t   srcOff = ((size_t)sn * Ndim + sp * 16) * 2;   // bytes, + j0*2
    // er staging: tid<64 -> sEE, tid in [64,128) -> sEF; [h][j] 16B chunks
    const int eh = (tid >> 4) & 3;
    const int ec = tid & 15;
    const unsigned erDst = (tid < 64 ? aEE : aEF) + (eh * TJ + ec * 4) * 4;
    const char* erSrc = ((tid < 64) ? (const char*)g_erE : (const char*)g_erF)
                        + ((size_t)(bb * NH + eh) * Ndim + ec * 4) * 4;  // + j0*4
    // ldmatrix lane base: row (lane&7), 16B chunk (lane>>3)
    const unsigned lb = (lane & 7) * XS_STRIDE + (lane >> 3) * 16;

    // prologue: stage tile 0
    {
        cp16(aXh + dstOff,      XThB + srcOff);
        cp16(aXh + dstOff + 16, XThB + srcOff + 16);
        if (tid < 128) cp16(erDst, erSrc);
        cp_commit();
    }

    uint2 mwA = mrowA[0];
    uint2 mwB = mrowB[0];

    for (int jt = 0; jt < NJT; jt++) {
        const int st = jt & 1;
        cp_wait0();
        __syncthreads();

        if (jt + 1 < NJT) {
            const size_t jb = (size_t)(jt + 1) * TJ * 2;       // bytes along j
            const unsigned so = (st ^ 1) * XS_BYTES + dstOff;
            cp16(aXh + so,      XThB + srcOff + jb);
            cp16(aXh + so + 16, XThB + srcOff + jb + 16);
            if (tid < 128)
                cp16(erDst + (st ^ 1) * ER_BYTES, erSrc + (size_t)(jt + 1) * TJ * 4);
        }
        cp_commit();

        uint2 nmwA = make_uint2(0, 0), nmwB = make_uint2(0, 0);
        if (jt + 1 < NJT) { nmwA = mrowA[jt + 1]; nmwB = mrowB[jt + 1]; }

        const ull* eE = (const ull*)(sEE[st] + hh * TJ);
        const ull* eF = (const ull*)(sEF[st] + hh * TJ);
        const unsigned xhB = aXh + st * XS_BYTES + lb;

#pragma unroll
        for (int ktp = 0; ktp < 2; ktp++) {
            const unsigned wA = ktp ? mwA.y : mwA.x;
            const unsigned wB = ktp ? mwB.y : mwB.x;

            unsigned aP[2][4];    // fp16x2 A fragments, s = 0,1 (two k16 chunks)
#pragma unroll
            for (int s = 0; s < 2; s++) {
                const int ix = ktp * 16 + s * 8 + q;     // j-pair index
                ull e0 = eE[ix], f0 = eF[ix];
                ull e1 = eE[ix + 4], f1 = eF[ix + 4];

                float2 pA0 = max2f(mul2(efAE, e0), mul2(efAF, f0));
                float2 pB0 = max2f(mul2(efBE, e0), mul2(efBF, f0));
                float2 pA1 = max2f(mul2(efAE, e1), mul2(efAF, f1));
                float2 pB1 = max2f(mul2(efBE, e1), mul2(efBF, f1));

                const unsigned bA = wA >> (s * 16 + q2);
                const unsigned bB = wB >> (s * 16 + q2);

                unsigned a0 = pack_f16x2(pA0.x, pA0.y);
                a0 &= ((bA & 1u) ? 0xFFFFu : 0u) | ((bA & 2u) ? 0xFFFF0000u : 0u);
                unsigned b0 = pack_f16x2(pB0.x, pB0.y);
                b0 &= ((bB & 1u) ? 0xFFFFu : 0u) | ((bB & 2u) ? 0xFFFF0000u : 0u);
                unsigned a1 = pack_f16x2(pA1.x, pA1.y);
                a1 &= ((bA & 256u) ? 0xFFFFu : 0u) | ((bA & 512u) ? 0xFFFF0000u : 0u);
                unsigned b1 = pack_f16x2(pB1.x, pB1.y);
                b1 &= ((bB & 256u) ? 0xFFFFu : 0u) | ((bB & 512u) ? 0xFFFF0000u : 0u);

                aP[s][0] = a0;
                aP[s][1] = b0;
                aP[s][2] = a1;
                aP[s][3] = b1;
            }

            const unsigned kb = ktp * 64;   // byte offset of this kt-pair along j
#pragma unroll
            for (int nt = 0; nt < 8; nt++) {
                const unsigned ro = nt * (8 * XS_STRIDE) + kb;
                unsigned bh0, bh1, bh2, bh3;
                ldsm4(bh0, bh1, bh2, bh3, xhB + ro);
                mma_f16(acc[nt], aP[0], bh0, bh1);
                mma_f16(acc[nt], aP[1], bh2, bh3);
            }
            // denominator: row-sums of the exact same fragments (B = ones)
            mma_f16(accD, aP[0], ONES16x2, ONES16x2);
            mma_f16(accD, aP[1], ONES16x2, ONES16x2);
        }
        mwA = nmwA;
        mwB = nmwB;
    }

    const float inv0 = 1.0f / accD[0];   // row iA den (all cols identical)
    const float inv1 = 1.0f / accD[2];   // row iA+8 den

    float* o0 = out + (size_t)((bb << 12) + iA) * (NH * FO) + hh * FO;
    float* o1 = o0 + (size_t)8 * (NH * FO);
#pragma unroll
    for (int nt = 0; nt < 8; nt++) {
        const int col = nt * 8 + q2;
        float2 bv = *(const float2*)&bias[hh * FO + col];
        float v00 = fmaf(acc[nt][0], inv0, bv.x);
        float v01 = fmaf(acc[nt][1], inv0, bv.y);
        float v10 = fmaf(acc[nt][2], inv1, bv.x);
        float v11 = fmaf(acc[nt][3], inv1, bv.y);
        v00 = v00 > 0.0f ? v00 : expm1f(v00);
        v01 = v01 > 0.0f ? v01 : expm1f(v01);
        v10 = v10 > 0.0f ? v10 : expm1f(v10);
        v11 = v11 > 0.0f ? v11 : expm1f(v11);
        *(float2*)&o0[col] = make_float2(v00, v01);
        *(float2*)&o1[col] = make_float2(v10, v11);
    }
}

// ---------------- launch ----------------
extern "C" void kernel_launch(void* const* d_in, const int* in_sizes, int n_in,
                              void* d_out, int out_size) {
    const int*   adj = (const int*)  d_in[0];  // (B,N,N) int32
    const float* h   = (const float*)d_in[1];  // (B,N,256)
    const float* W   = (const float*)d_in[2];  // (256,64)
    const float* Wl  = (const float*)d_in[3];  // (4,64)
    const float* Wr  = (const float*)d_in[4];  // (4,64)
    const float* bia = (const float*)d_in[5];  // (64,)
    float* out = (float*)d_out;                // (B,N,256)

    k_pack<<<1024, 256>>>(adj);
    k_gemm_xw<<<ROWS / 64, 256>>>(h, W);
    k_coef<<<ROWS / 4, 128>>>(Wl, Wr);
    k_attn<<<Bdim * (Ndim / TI), 256>>>(bia, out);
}